// round 15
// baseline (speedup 1.0000x reference)
#include <cuda_runtime.h>
#include <cuda_fp16.h>
#include <cuda_bf16.h>
#include <cstdint>

#define N_NODES  100000
#define N_EDGES  1200000
#define D        64
#define N_GRAPHS 256
#define TILE_M   128
#define LDA      68    // fp32 smem leading dim for h1 tile (conflict-free)

// ---------------- scratch (device globals; no allocation allowed) ----------
__device__ uint4    g_xh4[N_NODES * 8];    // node_feats as fp16 (12.8 MB)
__device__ uint4    g_aggh4[N_NODES * 8];  // fp16 aggregate (12.8 MB)
__device__ float    g_S[N_GRAPHS * D];     // per-graph sum of h2
__device__ int      g_cnt[N_GRAPHS];       // nodes per graph
__device__ uint32_t g_Wp[3 * 4096];        // packed bf16 (hi<<16|lo), XOR-swizzled

// ---------------- helpers ---------------------------------------------------
__device__ __forceinline__ uint32_t f2tf(float x) {
    uint32_t r; asm("cvt.rna.tf32.f32 %0, %1;" : "=r"(r) : "f"(x)); return r;
}
__device__ __forceinline__ void mma8(float* c, const uint32_t* a, uint32_t b0, uint32_t b1) {
    asm volatile("mma.sync.aligned.m16n8k8.row.col.f32.tf32.tf32.f32 "
                 "{%0,%1,%2,%3}, {%4,%5,%6,%7}, {%8,%9}, {%0,%1,%2,%3};"
                 : "+f"(c[0]), "+f"(c[1]), "+f"(c[2]), "+f"(c[3])
                 : "r"(a[0]), "r"(a[1]), "r"(a[2]), "r"(a[3]), "r"(b0), "r"(b1));
}

// ---------------- zero scratch ----------------------------------------------
__global__ void k_zero() {
    int i = blockIdx.x * blockDim.x + threadIdx.x;
    if (i < N_NODES * 8) g_aggh4[i] = make_uint4(0u, 0u, 0u, 0u);
    if (i < N_GRAPHS * D / 4)
        reinterpret_cast<float4*>(g_S)[i] = make_float4(0.f, 0.f, 0.f, 0.f);
    if (i < N_GRAPHS) g_cnt[i] = 0;
}

// ---------------- weight prep: bf16 hi/lo pack + XOR bank swizzle -----------
// g_Wp[sel*4096 + k*64 + j] = pack(W[k][ j ^ ((k&3)<<3) ])
__global__ void k_prepw(const float* __restrict__ Wg, const float* __restrict__ Wr,
                        const float* __restrict__ Wi) {
    int i = blockIdx.x * blockDim.x + threadIdx.x;
    if (i >= 3 * 4096) return;
    int sel = i >> 12, j = i & 4095;
    int k = j >> 6, n0 = j & 63;
    int n = n0 ^ ((k & 3) << 3);
    const float* W = sel == 0 ? Wg : (sel == 1 ? Wr : Wi);
    float w = W[k * 64 + n];
    __nv_bfloat16 hb = __float2bfloat16(w);
    float hf = __bfloat162float(hb);
    __nv_bfloat16 lb = __float2bfloat16(w - hf);
    g_Wp[i] = (((uint32_t)__bfloat16_as_ushort(hb)) << 16) |
              (uint32_t)__bfloat16_as_ushort(lb);
}

// ---------------- x -> fp16 -------------------------------------------------
__global__ void k_prepx(const float* __restrict__ x) {
    int i = blockIdx.x * blockDim.x + threadIdx.x;
    if (i >= N_NODES * 32) return;
    float2 f = reinterpret_cast<const float2*>(x)[i];
    reinterpret_cast<__half2*>(g_xh4)[i] = __float22half2_rn(f);
}

// ---------------- edge scatter: agg_h[dst] += xh[src]  (fp16) ---------------
// 8 lanes per edge; one uint4 (8 halves) per lane; fp16x2 vector reduction.
__global__ void k_edge(const int* __restrict__ src, const int* __restrict__ dst) {
    int t = blockIdx.x * blockDim.x + threadIdx.x;
    int e = t >> 3;
    int l = t & 7;
    if (e >= N_EDGES) return;
    int s = __ldg(&src[e]);
    int d = __ldg(&dst[e]);
    uint4 v = g_xh4[(size_t)s * 8 + l];
    uint4* a = &g_aggh4[(size_t)d * 8 + l];
    asm volatile("red.global.add.noftz.v4.f16x2 [%0], {%1, %2, %3, %4};"
                 :: "l"(a), "r"(v.x), "r"(v.y), "r"(v.z), "r"(v.w) : "memory");
}

// ---------------- fused node pipeline (tensor cores) ------------------------
// h1 = relu(agg@Wg + bg) + relu(x@Wr + br) ; h2 = relu(h1@Wi + bi)
// S[graph] += h2 ; cnt[graph] += 1
// 256 thr / 8 warps, 128-node tile, warp w owns rows [16w,16w+16).
// Weights: packed bf16 hi/lo in smem (swizzled). agg & x A-frags read
// directly from fp16 globals (L2-resident, exact in tf32).
__global__ void __launch_bounds__(256, 2) k_node(
        const int* __restrict__ gid,
        const float* __restrict__ bg, const float* __restrict__ br,
        const float* __restrict__ bi) {
    extern __shared__ float sm[];
    uint32_t* sW = (uint32_t*)sm;                  // 3*4096 packed weights
    float*    sH = sm + 3 * 4096;                  // TILE_M * LDA (h1 buffer)
    float*    sb = sH + TILE_M * LDA;              // 3 * 64 biases

    const int tid = threadIdx.x;
    const int node0 = blockIdx.x * TILE_M;

    // packed weights -> smem (uint4 copies)
    #pragma unroll
    for (int u = tid; u < 3 * 1024; u += 256)
        reinterpret_cast<uint4*>(sW)[u] = reinterpret_cast<const uint4*>(g_Wp)[u];
    if (tid < 64) { sb[tid] = bg[tid]; sb[64 + tid] = br[tid]; sb[128 + tid] = bi[tid]; }
    __syncthreads();

    const int warp = tid >> 5, lane = tid & 31;
    const int g = lane >> 2, t = lane & 3;
    const int row0 = warp * 16 + g;                // rows row0, row0+8
    const uint32_t* sWg = sW;
    const uint32_t* sWr = sW + 4096;
    const uint32_t* sWi = sW + 2 * 4096;

    const int nA = node0 + row0, nB = nA + 8;      // global node ids of lane's rows
    const bool vA = (nA < N_NODES), vB = (nB < N_NODES);
    const __half* aggA = (const __half*)g_aggh4 + (size_t)(vA ? nA : 0) * 64;
    const __half* aggB = (const __half*)g_aggh4 + (size_t)(vB ? nB : 0) * 64;
    const __half* xA   = (const __half*)g_xh4   + (size_t)(vA ? nA : 0) * 64;
    const __half* xB   = (const __half*)g_xh4   + (size_t)(vB ? nB : 0) * 64;

    // ---- GEMM1 (dual): acc1 = agg@Wg, acc2 = x@Wr ----
    float acc1[8][4], acc2[8][4];
    #pragma unroll
    for (int na = 0; na < 8; na++)
        #pragma unroll
        for (int j = 0; j < 4; j++) { acc1[na][j] = 0.f; acc2[na][j] = 0.f; }

    #pragma unroll
    for (int k0 = 0; k0 < 64; k0 += 8) {
        uint32_t aA[4], aX[4];
        aA[0] = f2tf(__half2float(__ldg(&aggA[k0 + t])));
        aA[1] = f2tf(__half2float(__ldg(&aggB[k0 + t])));
        aA[2] = f2tf(__half2float(__ldg(&aggA[k0 + t + 4])));
        aA[3] = f2tf(__half2float(__ldg(&aggB[k0 + t + 4])));
        aX[0] = f2tf(__half2float(__ldg(&xA[k0 + t])));
        aX[1] = f2tf(__half2float(__ldg(&xB[k0 + t])));
        aX[2] = f2tf(__half2float(__ldg(&xA[k0 + t + 4])));
        aX[3] = f2tf(__half2float(__ldg(&xB[k0 + t + 4])));
        #pragma unroll
        for (int na = 0; na < 8; na++) {
            int col = ((na ^ t) << 3) + g;         // swizzled column
            uint32_t wg0 = sWg[(k0 + t) * 64 + col];
            uint32_t wg1 = sWg[(k0 + t + 4) * 64 + col];
            uint32_t wr0 = sWr[(k0 + t) * 64 + col];
            uint32_t wr1 = sWr[(k0 + t + 4) * 64 + col];
            mma8(acc1[na], aA, wg0 & 0xFFFF0000u, wg1 & 0xFFFF0000u);
            mma8(acc1[na], aA, wg0 << 16,         wg1 << 16);
            mma8(acc2[na], aX, wr0 & 0xFFFF0000u, wr1 & 0xFFFF0000u);
            mma8(acc2[na], aX, wr0 << 16,         wr1 << 16);
        }
    }

    // ---- epilogue1: h1 = relu(acc1+bg) + relu(acc2+br) -> sH (own band) ----
    #pragma unroll
    for (int na = 0; na < 8; na++) {
        int c0 = na * 8 + 2 * t, c1 = c0 + 1;
        float v0 = fmaxf(acc1[na][0] + sb[c0], 0.f) + fmaxf(acc2[na][0] + sb[64 + c0], 0.f);
        float v1 = fmaxf(acc1[na][1] + sb[c1], 0.f) + fmaxf(acc2[na][1] + sb[64 + c1], 0.f);
        float v2 = fmaxf(acc1[na][2] + sb[c0], 0.f) + fmaxf(acc2[na][2] + sb[64 + c0], 0.f);
        float v3 = fmaxf(acc1[na][3] + sb[c1], 0.f) + fmaxf(acc2[na][3] + sb[64 + c1], 0.f);
        *reinterpret_cast<float2*>(&sH[row0 * LDA + c0])       = make_float2(v0, v1);
        *reinterpret_cast<float2*>(&sH[(row0 + 8) * LDA + c0]) = make_float2(v2, v3);
    }
    __syncwarp();

    // ---- GEMM2: h2 = relu(h1@Wi + bi) ----
    float acc[8][4];
    #pragma unroll
    for (int na = 0; na < 8; na++)
        #pragma unroll
        for (int j = 0; j < 4; j++) acc[na][j] = 0.f;

    #pragma unroll
    for (int k0 = 0; k0 < 64; k0 += 8) {
        uint32_t aH[4];
        aH[0] = f2tf(sH[row0 * LDA + k0 + t]);
        aH[1] = f2tf(sH[(row0 + 8) * LDA + k0 + t]);
        aH[2] = f2tf(sH[row0 * LDA + k0 + t + 4]);
        aH[3] = f2tf(sH[(row0 + 8) * LDA + k0 + t + 4]);
        #pragma unroll
        for (int na = 0; na < 8; na++) {
            int col = ((na ^ t) << 3) + g;
            uint32_t wi0 = sWi[(k0 + t) * 64 + col];
            uint32_t wi1 = sWi[(k0 + t + 4) * 64 + col];
            mma8(acc[na], aH, wi0 & 0xFFFF0000u, wi1 & 0xFFFF0000u);
            mma8(acc[na], aH, wi0 << 16,         wi1 << 16);
        }
    }

    // ---- epilogue2: scatter h2 into per-graph sums ----
    int gdA = vA ? __ldg(&gid[nA]) : 0;
    int gdB = vB ? __ldg(&gid[nB]) : 0;
    #pragma unroll
    for (int na = 0; na < 8; na++) {
        int c0 = na * 8 + 2 * t, c1 = c0 + 1;
        if (vA) {
            float p0 = fmaxf(acc[na][0] + sb[128 + c0], 0.f);
            float p1 = fmaxf(acc[na][1] + sb[128 + c1], 0.f);
            asm volatile("red.global.add.v2.f32 [%0], {%1, %2};"
                         :: "l"(&g_S[gdA * 64 + c0]), "f"(p0), "f"(p1) : "memory");
        }
        if (vB) {
            float p2 = fmaxf(acc[na][2] + sb[128 + c0], 0.f);
            float p3 = fmaxf(acc[na][3] + sb[128 + c1], 0.f);
            asm volatile("red.global.add.v2.f32 [%0], {%1, %2};"
                         :: "l"(&g_S[gdB * 64 + c0]), "f"(p2), "f"(p3) : "memory");
        }
    }
    if (t == 0) {
        if (vA) atomicAdd(&g_cnt[gdA], 1);
        if (vB) atomicAdd(&g_cnt[gdB], 1);
    }
}

// ---------------- final readout ---------------------------------------------
// out[g] = S[g] . (W_out @ W_pred) + cnt[g] * (b_out . W_pred) + b_pred
__global__ void __launch_bounds__(64) k_final(const float* __restrict__ Wo,
                                              const float* __restrict__ bo,
                                              const float* __restrict__ Wp,
                                              const float* __restrict__ bp,
                                              float* __restrict__ out) {
    __shared__ float red[4];
    int gr = blockIdx.x, k = threadIdx.x;   // k in [0,64)
    float wop = 0.f;
    #pragma unroll 16
    for (int m = 0; m < 128; m++) wop += __ldg(&Wo[k * 128 + m]) * __ldg(&Wp[m]);
    float p  = g_S[gr * 64 + k] * wop;
    float sc = bo[k] * Wp[k] + bo[k + 64] * Wp[k + 64];
    #pragma unroll
    for (int o = 16; o; o >>= 1) {
        p  += __shfl_xor_sync(0xffffffffu, p, o);
        sc += __shfl_xor_sync(0xffffffffu, sc, o);
    }
    if ((k & 31) == 0) { red[(k >> 5) * 2] = p; red[(k >> 5) * 2 + 1] = sc; }
    __syncthreads();
    if (k == 0)
        out[gr] = red[0] + red[2] + (float)g_cnt[gr] * (red[1] + red[3]) + bp[0];
}

// ---------------- launch ----------------------------------------------------
extern "C" void kernel_launch(void* const* d_in, const int* in_sizes, int n_in,
                              void* d_out, int out_size) {
    const float* node_feats = (const float*)d_in[0];
    // d_in[1] = edge_feats (unused by the reference)
    const int*   src = (const int*)d_in[2];
    const int*   dst = (const int*)d_in[3];
    const int*   gid = (const int*)d_in[4];
    const float* Wg  = (const float*)d_in[5];
    const float* bg  = (const float*)d_in[6];
    const float* Wr  = (const float*)d_in[7];
    const float* br  = (const float*)d_in[8];
    const float* Wi  = (const float*)d_in[9];
    const float* bi  = (const float*)d_in[10];
    const float* Wo  = (const float*)d_in[11];
    const float* bo  = (const float*)d_in[12];
    const float* Wp  = (const float*)d_in[13];
    const float* bp  = (const float*)d_in[14];
    float* out = (float*)d_out;

    const int smem_bytes = 3 * 4096 * 4 + TILE_M * LDA * 4 + 192 * 4;
    cudaFuncSetAttribute(k_node, cudaFuncAttributeMaxDynamicSharedMemorySize, smem_bytes);

    k_zero <<<(N_NODES * 8 + 255) / 256, 256>>>();
    k_prepw<<<48, 256>>>(Wg, Wr, Wi);
    k_prepx<<<(N_NODES * 32 + 255) / 256, 256>>>(node_feats);
    k_edge <<<(N_EDGES * 8 + 255) / 256, 256>>>(src, dst);
    k_node <<<(N_NODES + TILE_M - 1) / TILE_M, 256, smem_bytes>>>(gid, bg, br, bi);
    k_final<<<N_GRAPHS, 64>>>(Wo, bo, Wp, bp, out);
}

// round 17
// speedup vs baseline: 1.1122x; 1.1122x over previous
#include <cuda_runtime.h>
#include <cuda_fp16.h>
#include <cstdint>

#define N_NODES  100000
#define N_EDGES  1200000
#define D        64
#define N_GRAPHS 256
#define TILE_M   128
#define LDH      36            // half2 (u32) smem leading dim for h1 (conflict-free)
#define WSCALE   64.0f         // weights pre-scaled by 2^6 (lo plane stays normal)
#define INV_WS   (1.0f / 64.0f)

// ---------------- scratch (device globals; no allocation allowed) ----------
__device__ uint4    g_xh4[N_NODES * 8];    // node_feats as fp16 (12.8 MB)
__device__ uint4    g_aggh4[N_NODES * 8];  // fp16 aggregate (12.8 MB)
__device__ float    g_S[N_GRAPHS * D];     // per-graph sum of h2
__device__ int      g_cnt[N_GRAPHS];       // nodes per graph
__device__ uint32_t g_Whi[3 * 2048];       // fp16x2 weight hi plane, swizzled
__device__ uint32_t g_Wlo[3 * 2048];       // fp16x2 weight lo plane, swizzled

// ---------------- helpers ---------------------------------------------------
__device__ __forceinline__ void mma16(float* c, const uint32_t* a, uint32_t b0, uint32_t b1) {
    asm volatile("mma.sync.aligned.m16n8k16.row.col.f32.f16.f16.f32 "
                 "{%0,%1,%2,%3}, {%4,%5,%6,%7}, {%8,%9}, {%0,%1,%2,%3};"
                 : "+f"(c[0]), "+f"(c[1]), "+f"(c[2]), "+f"(c[3])
                 : "r"(a[0]), "r"(a[1]), "r"(a[2]), "r"(a[3]), "r"(b0), "r"(b1));
}
__device__ __forceinline__ uint32_t pack_h2(float lo, float hi) {
    uint32_t r;
    asm("cvt.rn.f16x2.f32 %0, %1, %2;" : "=r"(r) : "f"(hi), "f"(lo));
    return r;
}

// ---------------- zero scratch ----------------------------------------------
__global__ void k_zero() {
    int i = blockIdx.x * blockDim.x + threadIdx.x;
    if (i < N_NODES * 8) g_aggh4[i] = make_uint4(0u, 0u, 0u, 0u);
    if (i < N_GRAPHS * D / 4)
        reinterpret_cast<float4*>(g_S)[i] = make_float4(0.f, 0.f, 0.f, 0.f);
    if (i < N_GRAPHS) g_cnt[i] = 0;
}

// ---------------- weight prep: fp16 hi/lo (scaled), k-paired, XOR swizzle ---
// slot i = sel*2048 + k2*64 + n0 holds cols n = n0 ^ ((k2&3)<<3), k = 2*k2, 2*k2+1
__global__ void k_prepw(const float* __restrict__ Wg, const float* __restrict__ Wr,
                        const float* __restrict__ Wi) {
    int i = blockIdx.x * blockDim.x + threadIdx.x;
    if (i >= 3 * 2048) return;
    int sel = i >> 11, j = i & 2047;
    int k2 = j >> 6, n0 = j & 63;
    int n = n0 ^ ((k2 & 3) << 3);
    const float* W = sel == 0 ? Wg : (sel == 1 ? Wr : Wi);
    float we = W[(2 * k2) * 64 + n] * WSCALE;
    float wo = W[(2 * k2 + 1) * 64 + n] * WSCALE;
    __half he = __float2half_rn(we), ho = __float2half_rn(wo);
    __half le = __float2half_rn(we - __half2float(he));
    __half lo = __float2half_rn(wo - __half2float(ho));
    g_Whi[i] = ((uint32_t)__half_as_ushort(ho) << 16) | (uint32_t)__half_as_ushort(he);
    g_Wlo[i] = ((uint32_t)__half_as_ushort(lo) << 16) | (uint32_t)__half_as_ushort(le);
}

// ---------------- x -> fp16 -------------------------------------------------
__global__ void k_prepx(const float* __restrict__ x) {
    int i = blockIdx.x * blockDim.x + threadIdx.x;
    if (i >= N_NODES * 32) return;
    float2 f = reinterpret_cast<const float2*>(x)[i];
    reinterpret_cast<__half2*>(g_xh4)[i] = __float22half2_rn(f);
}

// ---------------- edge scatter: agg_h[dst] += xh[src]  (fp16) ---------------
__global__ void k_edge(const int* __restrict__ src, const int* __restrict__ dst) {
    int t = blockIdx.x * blockDim.x + threadIdx.x;
    int e = t >> 3;
    int l = t & 7;
    if (e >= N_EDGES) return;
    int s = __ldg(&src[e]);
    int d = __ldg(&dst[e]);
    uint4 v = g_xh4[(size_t)s * 8 + l];
    uint4* a = &g_aggh4[(size_t)d * 8 + l];
    asm volatile("red.global.add.noftz.v4.f16x2 [%0], {%1, %2, %3, %4};"
                 :: "l"(a), "r"(v.x), "r"(v.y), "r"(v.z), "r"(v.w) : "memory");
}

// ---------------- fused node pipeline (fp16 HMMA) ----------------------------
// h1 = relu(agg@Wg + bg) + relu(x@Wr + br) ; h2 = relu(h1@Wi + bi)
// S[graph] += h2 ; cnt[graph] += 1
// 256 thr / 8 warps, 128-node tile, warp w owns rows [16w,16w+16).
// Weights: fp16 hi/lo (pre-scaled x64) in smem; activations exact fp16 from
// global; h1 staged as half2 in smem; accumulators f32, rescaled by 1/64.
__global__ void __launch_bounds__(256, 2) k_node(
        const int* __restrict__ gid,
        const float* __restrict__ bg, const float* __restrict__ br,
        const float* __restrict__ bi) {
    extern __shared__ float sm[];
    uint32_t* sWhi = (uint32_t*)sm;                 // 3*2048
    uint32_t* sWlo = sWhi + 3 * 2048;               // 3*2048
    uint32_t* sH   = sWlo + 3 * 2048;               // TILE_M * LDH half2 words
    float*    sb   = (float*)(sH + TILE_M * LDH);   // 3*64 biases

    const int tid = threadIdx.x;
    const int node0 = blockIdx.x * TILE_M;

    #pragma unroll
    for (int u = tid; u < 3 * 512; u += 256) {
        reinterpret_cast<uint4*>(sWhi)[u] = reinterpret_cast<const uint4*>(g_Whi)[u];
        reinterpret_cast<uint4*>(sWlo)[u] = reinterpret_cast<const uint4*>(g_Wlo)[u];
    }
    if (tid < 64) { sb[tid] = bg[tid]; sb[64 + tid] = br[tid]; sb[128 + tid] = bi[tid]; }
    __syncthreads();

    const int warp = tid >> 5, lane = tid & 31;
    const int g = lane >> 2, t = lane & 3;
    const int row0 = warp * 16 + g;                 // rows row0, row0+8
    const uint32_t* sWg_hi = sWhi,           * sWg_lo = sWlo;
    const uint32_t* sWr_hi = sWhi + 2048,    * sWr_lo = sWlo + 2048;
    const uint32_t* sWi_hi = sWhi + 2 * 2048,* sWi_lo = sWlo + 2 * 2048;

    const int nA = node0 + row0, nB = nA + 8;
    const bool vA = (nA < N_NODES), vB = (nB < N_NODES);
    const __half* aggA = (const __half*)g_aggh4 + (size_t)(vA ? nA : 0) * 64;
    const __half* aggB = (const __half*)g_aggh4 + (size_t)(vB ? nB : 0) * 64;
    const __half* xA   = (const __half*)g_xh4   + (size_t)(vA ? nA : 0) * 64;
    const __half* xB   = (const __half*)g_xh4   + (size_t)(vB ? nB : 0) * 64;

    // ---- GEMM1 (dual): acc1 = agg@Wg', acc2 = x@Wr' ----
    float acc1[8][4], acc2[8][4];
    #pragma unroll
    for (int na = 0; na < 8; na++)
        #pragma unroll
        for (int j = 0; j < 4; j++) { acc1[na][j] = 0.f; acc2[na][j] = 0.f; }

    #pragma unroll
    for (int ks = 0; ks < 4; ks++) {                // k0 = ks*16
        uint32_t aA[4], aX[4];
        aA[0] = *(const uint32_t*)(aggA + ks * 16 + 2 * t);
        aA[1] = *(const uint32_t*)(aggB + ks * 16 + 2 * t);
        aA[2] = *(const uint32_t*)(aggA + ks * 16 + 8 + 2 * t);
        aA[3] = *(const uint32_t*)(aggB + ks * 16 + 8 + 2 * t);
        aX[0] = *(const uint32_t*)(xA + ks * 16 + 2 * t);
        aX[1] = *(const uint32_t*)(xB + ks * 16 + 2 * t);
        aX[2] = *(const uint32_t*)(xA + ks * 16 + 8 + 2 * t);
        aX[3] = *(const uint32_t*)(xB + ks * 16 + 8 + 2 * t);
        #pragma unroll
        for (int na = 0; na < 8; na++) {
            int col = ((na ^ t) << 3) + g;          // swizzled column
            int i0 = (ks * 8 + t) * 64 + col;
            int i1 = (ks * 8 + t + 4) * 64 + col;
            mma16(acc1[na], aA, sWg_hi[i0], sWg_hi[i1]);
            mma16(acc1[na], aA, sWg_lo[i0], sWg_lo[i1]);
            mma16(acc2[na], aX, sWr_hi[i0], sWr_hi[i1]);
            mma16(acc2[na], aX, sWr_lo[i0], sWr_lo[i1]);
        }
    }

    // ---- epilogue1: h1 = relu(acc1/64+bg) + relu(acc2/64+br) -> sH fp16 ----
    #pragma unroll
    for (int na = 0; na < 8; na++) {
        int c0 = na * 8 + 2 * t, c1 = c0 + 1;
        float v0 = fmaxf(acc1[na][0] * INV_WS + sb[c0], 0.f) + fmaxf(acc2[na][0] * INV_WS + sb[64 + c0], 0.f);
        float v1 = fmaxf(acc1[na][1] * INV_WS + sb[c1], 0.f) + fmaxf(acc2[na][1] * INV_WS + sb[64 + c1], 0.f);
        float v2 = fmaxf(acc1[na][2] * INV_WS + sb[c0], 0.f) + fmaxf(acc2[na][2] * INV_WS + sb[64 + c0], 0.f);
        float v3 = fmaxf(acc1[na][3] * INV_WS + sb[c1], 0.f) + fmaxf(acc2[na][3] * INV_WS + sb[64 + c1], 0.f);
        sH[row0 * LDH + na * 4 + t]       = pack_h2(v0, v1);
        sH[(row0 + 8) * LDH + na * 4 + t] = pack_h2(v2, v3);
    }
    __syncwarp();

    // ---- GEMM2: h2 = relu(h1@Wi' / 64 + bi) ----
    float acc[8][4];
    #pragma unroll
    for (int na = 0; na < 8; na++)
        #pragma unroll
        for (int j = 0; j < 4; j++) acc[na][j] = 0.f;

    #pragma unroll
    for (int ks = 0; ks < 4; ks++) {
        uint32_t aH[4];
        aH[0] = sH[row0 * LDH + ks * 8 + t];
        aH[1] = sH[(row0 + 8) * LDH + ks * 8 + t];
        aH[2] = sH[row0 * LDH + ks * 8 + 4 + t];
        aH[3] = sH[(row0 + 8) * LDH + ks * 8 + 4 + t];
        #pragma unroll
        for (int na = 0; na < 8; na++) {
            int col = ((na ^ t) << 3) + g;
            int i0 = (ks * 8 + t) * 64 + col;
            int i1 = (ks * 8 + t + 4) * 64 + col;
            mma16(acc[na], aH, sWi_hi[i0], sWi_hi[i1]);
            mma16(acc[na], aH, sWi_lo[i0], sWi_lo[i1]);
        }
    }

    // ---- epilogue2: scatter h2 into per-graph sums ----
    int gdA = vA ? __ldg(&gid[nA]) : 0;
    int gdB = vB ? __ldg(&gid[nB]) : 0;
    #pragma unroll
    for (int na = 0; na < 8; na++) {
        int c0 = na * 8 + 2 * t, c1 = c0 + 1;
        if (vA) {
            float p0 = fmaxf(acc[na][0] * INV_WS + sb[128 + c0], 0.f);
            float p1 = fmaxf(acc[na][1] * INV_WS + sb[128 + c1], 0.f);
            asm volatile("red.global.add.v2.f32 [%0], {%1, %2};"
                         :: "l"(&g_S[gdA * 64 + c0]), "f"(p0), "f"(p1) : "memory");
        }
        if (vB) {
            float p2 = fmaxf(acc[na][2] * INV_WS + sb[128 + c0], 0.f);
            float p3 = fmaxf(acc[na][3] * INV_WS + sb[128 + c1], 0.f);
            asm volatile("red.global.add.v2.f32 [%0], {%1, %2};"
                         :: "l"(&g_S[gdB * 64 + c0]), "f"(p2), "f"(p3) : "memory");
        }
    }
    if (t == 0) {
        if (vA) atomicAdd(&g_cnt[gdA], 1);
        if (vB) atomicAdd(&g_cnt[gdB], 1);
    }
}

// ---------------- final readout ---------------------------------------------
// out[g] = S[g] . (W_out @ W_pred) + cnt[g] * (b_out . W_pred) + b_pred
__global__ void __launch_bounds__(64) k_final(const float* __restrict__ Wo,
                                              const float* __restrict__ bo,
                                              const float* __restrict__ Wp,
                                              const float* __restrict__ bp,
                                              float* __restrict__ out) {
    __shared__ float red[4];
    int gr = blockIdx.x, k = threadIdx.x;   // k in [0,64)
    float wop = 0.f;
    #pragma unroll 16
    for (int m = 0; m < 128; m++) wop += __ldg(&Wo[k * 128 + m]) * __ldg(&Wp[m]);
    float p  = g_S[gr * 64 + k] * wop;
    float sc = bo[k] * Wp[k] + bo[k + 64] * Wp[k + 64];
    #pragma unroll
    for (int o = 16; o; o >>= 1) {
        p  += __shfl_xor_sync(0xffffffffu, p, o);
        sc += __shfl_xor_sync(0xffffffffu, sc, o);
    }
    if ((k & 31) == 0) { red[(k >> 5) * 2] = p; red[(k >> 5) * 2 + 1] = sc; }
    __syncthreads();
    if (k == 0)
        out[gr] = red[0] + red[2] + (float)g_cnt[gr] * (red[1] + red[3]) + bp[0];
}

// ---------------- launch ----------------------------------------------------
extern "C" void kernel_launch(void* const* d_in, const int* in_sizes, int n_in,
                              void* d_out, int out_size) {
    const float* node_feats = (const float*)d_in[0];
    // d_in[1] = edge_feats (unused by the reference)
    const int*   src = (const int*)d_in[2];
    const int*   dst = (const int*)d_in[3];
    const int*   gid = (const int*)d_in[4];
    const float* Wg  = (const float*)d_in[5];
    const float* bg  = (const float*)d_in[6];
    const float* Wr  = (const float*)d_in[7];
    const float* br  = (const float*)d_in[8];
    const float* Wi  = (const float*)d_in[9];
    const float* bi  = (const float*)d_in[10];
    const float* Wo  = (const float*)d_in[11];
    const float* bo  = (const float*)d_in[12];
    const float* Wp  = (const float*)d_in[13];
    const float* bp  = (const float*)d_in[14];
    float* out = (float*)d_out;

    const int smem_bytes = 2 * (3 * 2048) * 4 + TILE_M * LDH * 4 + 192 * 4;
    cudaFuncSetAttribute(k_node, cudaFuncAttributeMaxDynamicSharedMemorySize, smem_bytes);

    k_zero <<<(N_NODES * 8 + 255) / 256, 256>>>();
    k_prepw<<<24, 256>>>(Wg, Wr, Wi);
    k_prepx<<<(N_NODES * 32 + 255) / 256, 256>>>(node_feats);
    k_edge <<<(N_EDGES * 8 + 255) / 256, 256>>>(src, dst);
    k_node <<<(N_NODES + TILE_M - 1) / TILE_M, 256, smem_bytes>>>(gid, bg, br, bi);
    k_final<<<N_GRAPHS, 64>>>(Wo, bo, Wp, bp, out);
}